// round 12
// baseline (speedup 1.0000x reference)
#include <cuda_runtime.h>
#include <cstdint>
#include <math.h>

// Persistent single kernel, all SMs.
// Phase 1: grid-stride dot (exact R7 inner loop: smem-staged hidden, 8
//          independent __ldcs float4 per warp), energies -> d_out via st.cg.
// Grid barrier: ONE release-arrival per CTA + acquire-spin (two counters so
//          reset is race-free across CUDA-graph replays). This is ~600 atomic
//          ops once -- NOT the 131072-RMW storm that poisoned R3/R8.
// Phase 2: CTAs 0..63 softmax one batch each straight out of L2.

__device__ unsigned int g_barA;   // arrivals
__device__ unsigned int g_barB;   // reset rendezvous

__global__ void __launch_bounds__(256, 4)
attn_persistent_kernel(const float* __restrict__ hidden,   // [64, 1024]
                       const float* __restrict__ enc,      // [2048, 64, 1024]
                       float* __restrict__ out)            // [64, 2048]
{
    __shared__ float4 sh_h[256];
    __shared__ float  red[16];      // 8 warp maxes + 8 warp sums (phase 2)

    int tid  = threadIdx.x;
    int warp = tid >> 5;
    int lane = tid & 31;

    // ---------------- Phase 1: dot ----------------
    for (int w = blockIdx.x; w < 16384; w += gridDim.x) {
        int b      = w & 63;
        int schunk = w >> 6;

        __syncthreads();   // protect sh_h reuse across iterations
        sh_h[tid] = reinterpret_cast<const float4*>(hidden + (size_t)b * 1024)[tid];
        __syncthreads();

        int s = schunk * 8 + warp;
        const float4* row = reinterpret_cast<const float4*>(
            enc + ((size_t)s * 64 + b) * 1024);

        float acc = 0.0f;
#pragma unroll
        for (int i = 0; i < 8; i++) {
            float4 e  = __ldcs(&row[lane + i * 32]);
            float4 hv = sh_h[lane + i * 32];
            acc = fmaf(e.x, hv.x, acc);
            acc = fmaf(e.y, hv.y, acc);
            acc = fmaf(e.z, hv.z, acc);
            acc = fmaf(e.w, hv.w, acc);
        }
#pragma unroll
        for (int o = 16; o; o >>= 1)
            acc += __shfl_xor_sync(0xffffffffu, acc, o);

        if (lane == 0)
            asm volatile("st.global.cg.f32 [%0], %1;"
                         :: "l"(out + b * 2048 + s), "f"(acc) : "memory");
    }

    // ---------------- Grid barrier (one arrival per CTA) ----------------
    if (tid == 0) {
        unsigned int n = gridDim.x;
        asm volatile("red.release.gpu.global.add.u32 [%0], %1;"
                     :: "l"(&g_barA), "r"(1u) : "memory");
        unsigned int v;
        do {
            __nanosleep(64);
            asm volatile("ld.acquire.gpu.global.u32 %0, [%1];"
                         : "=r"(v) : "l"(&g_barA) : "memory");
        } while (v < n);
        // rendezvous B: last CTA through resets both counters (all CTAs have
        // already exited the A-spin once B reaches n, so reset cannot race).
        unsigned int old = atomicAdd(&g_barB, 1u);
        if (old == n - 1u) {
            g_barA = 0u;
            g_barB = 0u;
        }
    }
    __syncthreads();

    // ---------------- Phase 2: softmax, CTAs 0..63 ----------------
    int b = blockIdx.x;
    if (b >= 64) return;

    float4* p4 = reinterpret_cast<float4*>(out + (size_t)b * 2048);  // 512 float4

    float4 v0 = __ldcg(&p4[tid]);
    float4 v1 = __ldcg(&p4[tid + 256]);

    // --- block max ---
    float m = fmaxf(fmaxf(fmaxf(v0.x, v0.y), fmaxf(v0.z, v0.w)),
                    fmaxf(fmaxf(v1.x, v1.y), fmaxf(v1.z, v1.w)));
#pragma unroll
    for (int o = 16; o; o >>= 1)
        m = fmaxf(m, __shfl_xor_sync(0xffffffffu, m, o));
    if (lane == 0) red[warp] = m;
    __syncthreads();
    m = fmaxf(fmaxf(fmaxf(red[0], red[1]), fmaxf(red[2], red[3])),
              fmaxf(fmaxf(red[4], red[5]), fmaxf(red[6], red[7])));

    // --- exp + block sum ---
    v0.x = __expf(v0.x - m); v0.y = __expf(v0.y - m);
    v0.z = __expf(v0.z - m); v0.w = __expf(v0.w - m);
    v1.x = __expf(v1.x - m); v1.y = __expf(v1.y - m);
    v1.z = __expf(v1.z - m); v1.w = __expf(v1.w - m);
    float s = (v0.x + v0.y) + (v0.z + v0.w) + (v1.x + v1.y) + (v1.z + v1.w);
#pragma unroll
    for (int o = 16; o; o >>= 1)
        s += __shfl_xor_sync(0xffffffffu, s, o);
    if (lane == 0) red[8 + warp] = s;
    __syncthreads();
    float inv = 1.0f / (((red[8] + red[9]) + (red[10] + red[11])) +
                        ((red[12] + red[13]) + (red[14] + red[15])));

    v0.x *= inv; v0.y *= inv; v0.z *= inv; v0.w *= inv;
    v1.x *= inv; v1.y *= inv; v1.z *= inv; v1.w *= inv;
    p4[tid]       = v0;
    p4[tid + 256] = v1;
}

extern "C" void kernel_launch(void* const* d_in, const int* in_sizes, int n_in,
                              void* d_out, int out_size)
{
    const float* hidden = (const float*)d_in[0];   // [1, 64, 1024]
    const float* enc    = (const float*)d_in[1];   // [2048, 64, 1024]
    float* out          = (float*)d_out;           // [64, 1, 2048]

    // Grid sized to guaranteed co-residency (required by the grid barrier).
    int dev = 0, sms = 148, occ = 4;
    cudaGetDevice(&dev);
    cudaDeviceGetAttribute(&sms, cudaDevAttrMultiProcessorCount, dev);
    cudaOccupancyMaxActiveBlocksPerMultiprocessor(
        &occ, attn_persistent_kernel, 256, 0);
    int grid = sms * occ;
    if (grid > 16384) grid = 16384;
    if (grid < 64)    grid = 64;     // phase 2 needs 64 CTAs

    attn_persistent_kernel<<<grid, 256>>>(hidden, enc, out);
}